// round 12
// baseline (speedup 1.0000x reference)
#include <cuda_runtime.h>
#include <cstdint>

#define B_  50
#define T_  2048
#define D_  65
#define G4  260
#define BT  (B_ * T_)
#define KP  68          // K padded to 17*4
#define NL  3
#define NW  (T_ + 2)
#define NB  2           // batches per CTA
#define NCTA (B_ / NB)  // 25

// Precomputed x@W + b : [B*T, 260]
__device__ float g_xw[(size_t)BT * G4];
// Top-layer hidden states for dense epilogue: [B*T, 65]
__device__ float g_hs[(size_t)BT * D_];

// ---------------------------------------------------------------------------
__device__ __forceinline__ void ffma2(uint64_t& acc, uint64_t a, uint64_t b) {
    asm("fma.rn.f32x2 %0, %1, %2, %0;" : "+l"(acc) : "l"(a), "l"(b));
}
__device__ __forceinline__ uint64_t fadd2(uint64_t a, uint64_t b) {
    uint64_t r;
    asm("add.rn.f32x2 %0, %1, %2;" : "=l"(r) : "l"(a), "l"(b));
    return r;
}
__device__ __forceinline__ float hsum2(uint64_t v) {
    float lo, hi;
    asm("mov.b64 {%0, %1}, %2;" : "=f"(lo), "=f"(hi) : "l"(v));
    return lo + hi;
}
__device__ __forceinline__ uint64_t pack2(float lo, float hi) {
    uint64_t r;
    asm("mov.b64 %0, {%1, %2};" : "=l"(r) : "f"(lo), "f"(hi));
    return r;
}
__device__ __forceinline__ float tanh_fast(float x) {
    float e = __expf(2.0f * x);
    return fmaf(-2.0f, __fdividef(1.0f, 1.0f + e), 1.0f);
}

// load padded weight column into 34 packed regs
__device__ __forceinline__ void load_col(uint64_t* Wc,
                                         const float* __restrict__ M, int col) {
#pragma unroll
    for (int i = 0; i < 34; i++) {
        int k0 = 2 * i, k1 = 2 * i + 1;
        float w0 = (k0 < D_) ? M[(size_t)k0 * G4 + col] : 0.0f;
        float w1 = (k1 < D_) ? M[(size_t)k1 * G4 + col] : 0.0f;
        Wc[i] = pack2(w0, w1);
    }
}

__device__ __forceinline__ float dot68(const float* __restrict__ src,
                                       const uint64_t* __restrict__ Wc) {
    uint64_t a0 = 0, a1 = 0;
    const ulonglong2* s2 = reinterpret_cast<const ulonglong2*>(src);
#pragma unroll
    for (int i = 0; i < 17; i++) {
        ulonglong2 v = s2[i];
        ffma2(a0, v.x, Wc[2 * i]);
        ffma2(a1, v.y, Wc[2 * i + 1]);
    }
    return hsum2(fadd2(a0, a1));
}

// ---------------------------------------------------------------------------
__global__ void dummy_kernel() {}

// ---------------------------------------------------------------------------
// GEMM: g_xw[r, c] = x[r,:] @ W[:,c] + b[c]
// ---------------------------------------------------------------------------
#define GR 128
__global__ void __launch_bounds__(G4, 2) gemm_xw_kernel(
    const float* __restrict__ x, const float* __restrict__ W,
    const float* __restrict__ b)
{
    __shared__ __align__(16) float xs[2][32][KP];
    const int c = threadIdx.x;
    uint64_t Wc[34];
    load_col(Wc, W, c);
    const float bc = b[c];
    const size_t row0 = (size_t)blockIdx.x * GR;

    for (int i = c; i < 32 * KP; i += G4) {
        int r = i / KP, cc = i % KP;
        xs[0][r][cc] = (cc < D_) ? x[(row0 + r) * D_ + cc] : 0.0f;
    }
    __syncthreads();

    for (int ch = 0; ch < GR / 32; ch++) {
        int buf = ch & 1;
        if (ch + 1 < GR / 32) {
            for (int i = c; i < 32 * KP; i += G4) {
                int r = i / KP, cc = i % KP;
                xs[buf ^ 1][r][cc] =
                    (cc < D_) ? x[(row0 + (ch + 1) * 32 + r) * D_ + cc] : 0.0f;
            }
        }
        for (int r = 0; r < 32; r++)
            g_xw[(row0 + ch * 32 + r) * G4 + c] = bc + dot68(xs[buf][r], Wc);
        __syncthreads();
    }
}

// ---------------------------------------------------------------------------
// LSTM: wavefront-in-thread + 2 batches per CTA.
// 25 CTAs x 260 threads; tid = 4*unit + gate. Weight columns (136 regs)
// shared across both batches; 10 independent FMA chains + 2 gate tails
// per wave give the ILP needed to lift IPC at 2-3 warps/SMSP.
// ---------------------------------------------------------------------------
__global__ void __launch_bounds__(G4, 1) lstm_kernel(
    const float* __restrict__ W,
    const float* __restrict__ U,
    const float* __restrict__ b)
{
    __shared__ __align__(16) float hs[NB][NL][2][KP];  // [batch][layer][parity]

    const int tid  = threadIdx.x;
    const int j    = tid >> 2;       // unit 0..64
    const int g    = tid & 3;        // gate 0=i 1=f 2=g 3=o
    const int lane = tid & 31;
    const int base = lane & ~3;
    const unsigned mask = (tid >= 256) ? 0xFu : 0xFFFFFFFFu;
    const int col = g * D_ + j;
    const int bA  = 2 * blockIdx.x, bB = bA + 1;

    uint64_t Wc[34], Uc[34];
    load_col(Wc, W, col);
    load_col(Uc, U, col);
    const float bcol = b[col];
    const float ak = (g == 2) ?  2.0f : -1.0f;
    const float am = (g == 2) ? -2.0f :  1.0f;
    const float aa = (g == 2) ?  1.0f :  0.0f;

    for (int i = tid; i < NB * NL * 2 * KP; i += G4) ((float*)hs)[i] = 0.0f;
    float cA0 = 0.f, cA1 = 0.f, cA2 = 0.f;
    float cB0 = 0.f, cB1 = 0.f, cB2 = 0.f;

    const float* xwpA = g_xw + (size_t)bA * T_ * G4 + col;
    const float* xwpB = g_xw + (size_t)bB * T_ * G4 + col;
    float* houtA = g_hs + (size_t)bA * T_ * D_;
    float* houtB = g_hs + (size_t)bB * T_ * D_;
    float xwvA = xwpA[0], xwvB = xwpB[0];
    __syncthreads();

    for (int w = 0; w < NW; w++) {
        const int rd = (w & 1) ^ 1;
        const int wr = w & 1;
        const int tpf = (w + 1 < T_) ? (w + 1) : (T_ - 1);
        float xwnA = xwpA[(size_t)tpf * G4];
        float xwnB = xwpB[(size_t)tpf * G4];

        // ---- 10 dots over 6 shared vectors, one fused loop ---------------
        uint64_t Aa = 0, Ba = 0, Ea = 0, Da = 0, Fa = 0;   // batch A
        uint64_t Ab = 0, Bb = 0, Eb = 0, Db = 0, Fb = 0;   // batch B
        {
            const ulonglong2* a0 =
                reinterpret_cast<const ulonglong2*>(hs[0][0][rd]);
            const ulonglong2* a1 =
                reinterpret_cast<const ulonglong2*>(hs[0][1][rd]);
            const ulonglong2* a2 =
                reinterpret_cast<const ulonglong2*>(hs[0][2][rd]);
            const ulonglong2* b0 =
                reinterpret_cast<const ulonglong2*>(hs[1][0][rd]);
            const ulonglong2* b1 =
                reinterpret_cast<const ulonglong2*>(hs[1][1][rd]);
            const ulonglong2* b2 =
                reinterpret_cast<const ulonglong2*>(hs[1][2][rd]);
#pragma unroll
            for (int i = 0; i < 17; i++) {
                ulonglong2 vA0 = a0[i], vA1 = a1[i], vA2 = a2[i];
                ulonglong2 vB0 = b0[i], vB1 = b1[i], vB2 = b2[i];
                uint64_t u0 = Uc[2 * i], u1 = Uc[2 * i + 1];
                uint64_t w0 = Wc[2 * i], w1 = Wc[2 * i + 1];
                ffma2(Aa, vA0.x, u0); ffma2(Aa, vA0.y, u1);   // l0: U.h0
                ffma2(Ba, vA0.x, w0); ffma2(Ba, vA0.y, w1);   // l1: W.h0
                ffma2(Ea, vA1.x, u0); ffma2(Ea, vA1.y, u1);   // l1: U.h1
                ffma2(Da, vA1.x, w0); ffma2(Da, vA1.y, w1);   // l2: W.h1
                ffma2(Fa, vA2.x, u0); ffma2(Fa, vA2.y, u1);   // l2: U.h2
                ffma2(Ab, vB0.x, u0); ffma2(Ab, vB0.y, u1);
                ffma2(Bb, vB0.x, w0); ffma2(Bb, vB0.y, w1);
                ffma2(Eb, vB1.x, u0); ffma2(Eb, vB1.y, u1);
                ffma2(Db, vB1.x, w0); ffma2(Db, vB1.y, w1);
                ffma2(Fb, vB2.x, u0); ffma2(Fb, vB2.y, u1);
            }
        }
        float zA0 = xwvA + hsum2(Aa);
        float zA1 = bcol + hsum2(Ba) + hsum2(Ea);
        float zA2 = bcol + hsum2(Da) + hsum2(Fa);
        float zB0 = xwvB + hsum2(Ab);
        float zB1 = bcol + hsum2(Bb) + hsum2(Eb);
        float zB2 = bcol + hsum2(Db) + hsum2(Fb);

        // ---- activations (two independent chains interleave) -------------
        float aA0 = fmaf(am, __fdividef(1.0f, 1.0f + __expf(ak * zA0)), aa);
        float aA1 = fmaf(am, __fdividef(1.0f, 1.0f + __expf(ak * zA1)), aa);
        float aA2 = fmaf(am, __fdividef(1.0f, 1.0f + __expf(ak * zA2)), aa);
        float aB0 = fmaf(am, __fdividef(1.0f, 1.0f + __expf(ak * zB0)), aa);
        float aB1 = fmaf(am, __fdividef(1.0f, 1.0f + __expf(ak * zB1)), aa);
        float aB2 = fmaf(am, __fdividef(1.0f, 1.0f + __expf(ak * zB2)), aa);

        // ---- gate gathers -------------------------------------------------
        float iA0 = __shfl_sync(mask, aA0, base + 0);
        float fA0 = __shfl_sync(mask, aA0, base + 1);
        float gA0 = __shfl_sync(mask, aA0, base + 2);
        float oA0 = __shfl_sync(mask, aA0, base + 3);
        float iA1 = __shfl_sync(mask, aA1, base + 0);
        float fA1 = __shfl_sync(mask, aA1, base + 1);
        float gA1 = __shfl_sync(mask, aA1, base + 2);
        float oA1 = __shfl_sync(mask, aA1, base + 3);
        float iA2 = __shfl_sync(mask, aA2, base + 0);
        float fA2 = __shfl_sync(mask, aA2, base + 1);
        float gA2 = __shfl_sync(mask, aA2, base + 2);
        float oA2 = __shfl_sync(mask, aA2, base + 3);
        float iB0 = __shfl_sync(mask, aB0, base + 0);
        float fB0 = __shfl_sync(mask, aB0, base + 1);
        float gB0 = __shfl_sync(mask, aB0, base + 2);
        float oB0 = __shfl_sync(mask, aB0, base + 3);
        float iB1 = __shfl_sync(mask, aB1, base + 0);
        float fB1 = __shfl_sync(mask, aB1, base + 1);
        float gB1 = __shfl_sync(mask, aB1, base + 2);
        float oB1 = __shfl_sync(mask, aB1, base + 3);
        float iB2 = __shfl_sync(mask, aB2, base + 0);
        float fB2 = __shfl_sync(mask, aB2, base + 1);
        float gB2 = __shfl_sync(mask, aB2, base + 2);
        float oB2 = __shfl_sync(mask, aB2, base + 3);

        if (g == 0) {
            if (w < T_) {
                cA0 = fmaf(fA0, cA0, iA0 * gA0);
                cB0 = fmaf(fB0, cB0, iB0 * gB0);
                hs[0][0][wr][j] = oA0 * tanh_fast(cA0);
                hs[1][0][wr][j] = oB0 * tanh_fast(cB0);
            }
            if (w >= 1 && w <= T_) {
                cA1 = fmaf(fA1, cA1, iA1 * gA1);
                cB1 = fmaf(fB1, cB1, iB1 * gB1);
                hs[0][1][wr][j] = oA1 * tanh_fast(cA1);
                hs[1][1][wr][j] = oB1 * tanh_fast(cB1);
            }
            if (w >= 2) {
                cA2 = fmaf(fA2, cA2, iA2 * gA2);
                cB2 = fmaf(fB2, cB2, iB2 * gB2);
                float hA = oA2 * tanh_fast(cA2);
                float hB = oB2 * tanh_fast(cB2);
                hs[0][2][wr][j] = hA;
                hs[1][2][wr][j] = hB;
                houtA[(size_t)(w - 2) * D_ + j] = hA;
                houtB[(size_t)(w - 2) * D_ + j] = hB;
            }
        }
        __syncthreads();                    // one barrier per wave
        xwvA = xwnA; xwvB = xwnB;
    }
}

// ---------------------------------------------------------------------------
// Dense(65): out[r,:] = g_hs[r,:] @ Wd + bd
// ---------------------------------------------------------------------------
#define DR 64
__global__ void __launch_bounds__(520, 1) dense_kernel(
    const float* __restrict__ Wd,
    const float* __restrict__ bd,
    float* __restrict__ out)
{
    __shared__ __align__(16) float hrow[DR][KP];
    const int tx  = threadIdx.x;
    const int ty  = threadIdx.y;
    const int tid = ty * D_ + tx;

    uint64_t Wc[34];
#pragma unroll
    for (int i = 0; i < 34; i++) {
        int k0 = 2 * i, k1 = 2 * i + 1;
        float w0 = (k0 < D_) ? Wd[(size_t)k0 * D_ + tx] : 0.0f;
        float w1 = (k1 < D_) ? Wd[(size_t)k1 * D_ + tx] : 0.0f;
        Wc[i] = pack2(w0, w1);
    }
    const float bc = bd[tx];
    const size_t row0 = (size_t)blockIdx.x * DR;

    for (int i = tid; i < DR * KP; i += 520) {
        int r = i / KP, cc = i % KP;
        hrow[r][cc] = (cc < D_) ? g_hs[(row0 + r) * D_ + cc] : 0.0f;
    }
    __syncthreads();

    for (int r = ty; r < DR; r += 8)
        out[(row0 + r) * D_ + tx] = bc + dot68(hrow[r], Wc);
}

// ---------------------------------------------------------------------------
extern "C" void kernel_launch(void* const* d_in, const int* in_sizes, int n_in,
                              void* d_out, int out_size)
{
    const float* x  = (const float*)d_in[0];
    const float* W  = (const float*)d_in[1];
    const float* U  = (const float*)d_in[2];
    const float* b  = (const float*)d_in[3];
    const float* Wd = (const float*)d_in[4];
    const float* bd = (const float*)d_in[5];
    float* out = (float*)d_out;

    gemm_xw_kernel<<<BT / GR, G4>>>(x, W, b);
    dummy_kernel<<<1, 32>>>();     // keep ncu capture slot (idx 3) on lstm
    dummy_kernel<<<1, 32>>>();
    lstm_kernel<<<NCTA, G4>>>(W, U, b);
    dense_kernel<<<BT / DR, dim3(D_, 8)>>>(Wd, bd, out);
}

// round 16
// speedup vs baseline: 1.5677x; 1.5677x over previous
#include <cuda_runtime.h>
#include <cstdint>

#define B_  50
#define T_  2048
#define D_  65
#define G4  260
#define BT  (B_ * T_)
#define KPH 72          // hs row padding (main reads 68, sidecar quarters + row64)
#define NL  3
#define NW  (T_ + 2)
#define GR  128
#define DR  64

#if defined(__CUDACC_VER_MAJOR__) && (__CUDACC_VER_MAJOR__ > 12 || (__CUDACC_VER_MAJOR__ == 12 && __CUDACC_VER_MINOR__ >= 4))
#define LSTM_NREG __maxnreg__(232)
#else
#define LSTM_NREG
#endif

__device__ float g_xw[(size_t)BT * G4];   // x@W + b
__device__ float g_hs[(size_t)BT * D_];   // top-layer h

// ---------------------------------------------------------------------------
__device__ __forceinline__ void ffma2(uint64_t& acc, uint64_t a, uint64_t b) {
    asm("fma.rn.f32x2 %0, %1, %2, %0;" : "+l"(acc) : "l"(a), "l"(b));
}
__device__ __forceinline__ uint64_t fadd2(uint64_t a, uint64_t b) {
    uint64_t r;
    asm("add.rn.f32x2 %0, %1, %2;" : "=l"(r) : "l"(a), "l"(b));
    return r;
}
__device__ __forceinline__ float hsum2(uint64_t v) {
    float lo, hi;
    asm("mov.b64 {%0, %1}, %2;" : "=f"(lo), "=f"(hi) : "l"(v));
    return lo + hi;
}
__device__ __forceinline__ uint64_t pack2(float lo, float hi) {
    uint64_t r;
    asm("mov.b64 %0, {%1, %2};" : "=l"(r) : "f"(lo), "f"(hi));
    return r;
}
__device__ __forceinline__ float tanh_fast(float x) {
    float e = __expf(2.0f * x);
    return fmaf(-2.0f, __fdividef(1.0f, 1.0f + e), 1.0f);
}
__device__ __forceinline__ float act_f(float k, float m, float a, float z) {
    return fmaf(m, __fdividef(1.0f, 1.0f + __expf(k * z)), a);
}

__device__ __forceinline__ void load_col(uint64_t* Wc,
                                         const float* __restrict__ M, int col) {
#pragma unroll
    for (int i = 0; i < 34; i++) {
        int k0 = 2 * i, k1 = 2 * i + 1;
        float w0 = (k0 < D_) ? M[(size_t)k0 * G4 + col] : 0.0f;
        float w1 = (k1 < D_) ? M[(size_t)k1 * G4 + col] : 0.0f;
        Wc[i] = pack2(w0, w1);
    }
}

__device__ __forceinline__ float dot68(const float* __restrict__ src,
                                       const uint64_t* __restrict__ Wc) {
    uint64_t a0 = 0, a1 = 0;
    const ulonglong2* s2 = reinterpret_cast<const ulonglong2*>(src);
#pragma unroll
    for (int i = 0; i < 17; i++) {
        ulonglong2 v = s2[i];
        ffma2(a0, v.x, Wc[2 * i]);
        ffma2(a1, v.y, Wc[2 * i + 1]);
    }
    return hsum2(fadd2(a0, a1));
}

// ---------------------------------------------------------------------------
__global__ void dummy_kernel() {}

// ---------------------------------------------------------------------------
// GEMM: g_xw[r, c] = x[r,:] @ W[:,c] + b[c]
// ---------------------------------------------------------------------------
__global__ void __launch_bounds__(G4, 2) gemm_xw_kernel(
    const float* __restrict__ x, const float* __restrict__ W,
    const float* __restrict__ b)
{
    __shared__ __align__(16) float xs[2][32][68];
    const int c = threadIdx.x;
    uint64_t Wc[34];
    load_col(Wc, W, c);
    const float bc = b[c];
    const size_t row0 = (size_t)blockIdx.x * GR;

    for (int i = c; i < 32 * 68; i += G4) {
        int r = i / 68, cc = i % 68;
        xs[0][r][cc] = (cc < D_) ? x[(row0 + r) * D_ + cc] : 0.0f;
    }
    __syncthreads();

    for (int ch = 0; ch < GR / 32; ch++) {
        int buf = ch & 1;
        if (ch + 1 < GR / 32) {
            for (int i = c; i < 32 * 68; i += G4) {
                int r = i / 68, cc = i % 68;
                xs[buf ^ 1][r][cc] =
                    (cc < D_) ? x[(row0 + (ch + 1) * 32 + r) * D_ + cc] : 0.0f;
            }
        }
        for (int r = 0; r < 32; r++)
            g_xw[(row0 + ch * 32 + r) * G4 + c] = bc + dot68(xs[buf][r], Wc);
        __syncthreads();
    }
}

// ---------------------------------------------------------------------------
// LSTM wavefront, 256 threads (8 balanced warps). tid = 4*unit + gate for
// units 0..63; unit 64 handled by warp 0 lanes 0..15 as a K-quartered
// sidecar (weights in regs; 256-reg budget at 8 warps). One barrier/wave.
// ---------------------------------------------------------------------------
__global__ void LSTM_NREG lstm_kernel(
    const float* __restrict__ W,
    const float* __restrict__ U,
    const float* __restrict__ b)
{
    __shared__ __align__(16) float hs[NL][2][KPH];

    const int tid  = threadIdx.x;           // 0..255
    const int bb   = blockIdx.x;
    const int j    = tid >> 2;              // unit 0..63
    const int g    = tid & 3;               // gate 0=i 1=f 2=g 3=o
    const int lane = tid & 31;
    const int base = lane & ~3;
    const unsigned FULL = 0xFFFFFFFFu;
    const int col = g * D_ + j;

    uint64_t Wc[34], Uc[34];
    load_col(Wc, W, col);
    load_col(Uc, U, col);
    const float bcol = b[col];
    const float ak = (g == 2) ?  2.0f : -1.0f;
    const float am = (g == 2) ? -2.0f :  1.0f;
    const float aa = (g == 2) ?  1.0f :  0.0f;

    // ---- sidecar setup: lanes 0..15 own unit 64 (gate l>>2, K-quarter l&3)
    const bool side = (tid < 16);
    const int g64 = (tid >> 2) & 3;
    const int qq  = tid & 3;
    const int col64 = g64 * D_ + 64;
    uint64_t sW[8], sU[8];
#pragma unroll
    for (int i = 0; i < 8; i++) {
        int k0 = qq * 16 + 2 * i, k1 = k0 + 1;   // rows 0..63
        sW[i] = side ? pack2(W[(size_t)k0 * G4 + col64],
                             W[(size_t)k1 * G4 + col64]) : 0;
        sU[i] = side ? pack2(U[(size_t)k0 * G4 + col64],
                             U[(size_t)k1 * G4 + col64]) : 0;
    }
    float w64r = 0.f, u64r = 0.f;                // row-64 weights (qq==3 lane)
    if (side && qq == 3) {
        w64r = W[(size_t)64 * G4 + col64];
        u64r = U[(size_t)64 * G4 + col64];
    }
    const float b64  = b[col64];
    const float ak64 = (g64 == 2) ?  2.0f : -1.0f;
    const float am64 = (g64 == 2) ? -2.0f :  1.0f;
    const float aa64 = (g64 == 2) ?  1.0f :  0.0f;

    for (int i = tid; i < NL * 2 * KPH; i += 256) ((float*)hs)[i] = 0.0f;
    float c0 = 0.f, c1 = 0.f, c2 = 0.f;          // writer lanes (g==0)
    float c640 = 0.f, c641 = 0.f, c642 = 0.f;    // tid==0

    const float* xwp   = g_xw + (size_t)bb * T_ * G4 + col;
    const float* xwp64 = g_xw + (size_t)bb * T_ * G4 + col64;
    float*       hout  = g_hs + (size_t)bb * T_ * D_;
    float xwv   = xwp[0];
    float xwv64 = (side && qq == 0) ? xwp64[0] : 0.0f;
    __syncthreads();

    for (int w = 0; w < NW; w++) {
        const int rd = (w & 1) ^ 1;
        const int wr = w & 1;
        const int tpf = (w + 1 < T_) ? (w + 1) : (T_ - 1);
        float xwn   = xwp[(size_t)tpf * G4];
        float xwn64 = (side && qq == 0) ? xwp64[(size_t)tpf * G4] : 0.0f;

        // ---- main: 5 dots over 3 shared vectors, 10 acc chains ----------
        uint64_t A0 = 0, A1 = 0, B0 = 0, B1 = 0, E0 = 0, E1 = 0;
        uint64_t D0 = 0, D1 = 0, F0 = 0, F1 = 0;
        {
            const ulonglong2* p0 =
                reinterpret_cast<const ulonglong2*>(hs[0][rd]);
            const ulonglong2* p1 =
                reinterpret_cast<const ulonglong2*>(hs[1][rd]);
            const ulonglong2* p2 =
                reinterpret_cast<const ulonglong2*>(hs[2][rd]);
#pragma unroll
            for (int i = 0; i < 17; i++) {
                ulonglong2 v0 = p0[i], v1 = p1[i], v2 = p2[i];
                ffma2(A0, v0.x, Uc[2 * i]); ffma2(A1, v0.y, Uc[2 * i + 1]);
                ffma2(B0, v0.x, Wc[2 * i]); ffma2(B1, v0.y, Wc[2 * i + 1]);
                ffma2(E0, v1.x, Uc[2 * i]); ffma2(E1, v1.y, Uc[2 * i + 1]);
                ffma2(D0, v1.x, Wc[2 * i]); ffma2(D1, v1.y, Wc[2 * i + 1]);
                ffma2(F0, v2.x, Uc[2 * i]); ffma2(F1, v2.y, Uc[2 * i + 1]);
            }
        }
        float z0 = xwv + hsum2(fadd2(A0, A1));
        float z1 = bcol + hsum2(fadd2(B0, B1)) + hsum2(fadd2(E0, E1));
        float z2 = bcol + hsum2(fadd2(D0, D1)) + hsum2(fadd2(F0, F1));

        float act0 = act_f(ak, am, aa, z0);
        float act1 = act_f(ak, am, aa, z1);
        float act2 = act_f(ak, am, aa, z2);

        // gate gathers (writer's own act IS the i gate — only f,g,o shfl'd)
        float f0 = __shfl_sync(FULL, act0, base + 1);
        float g0 = __shfl_sync(FULL, act0, base + 2);
        float o0 = __shfl_sync(FULL, act0, base + 3);
        float f1 = __shfl_sync(FULL, act1, base + 1);
        float g1 = __shfl_sync(FULL, act1, base + 2);
        float o1 = __shfl_sync(FULL, act1, base + 3);
        float f2 = __shfl_sync(FULL, act2, base + 1);
        float g2 = __shfl_sync(FULL, act2, base + 2);
        float o2 = __shfl_sync(FULL, act2, base + 3);

        // ---- sidecar: unit 64 (warp 0 lanes 0..15) ----------------------
        if (side) {
            const unsigned SM = 0xFFFFu;
            const ulonglong2* q0 =
                reinterpret_cast<const ulonglong2*>(&hs[0][rd][16 * qq]);
            const ulonglong2* q1 =
                reinterpret_cast<const ulonglong2*>(&hs[1][rd][16 * qq]);
            const ulonglong2* q2 =
                reinterpret_cast<const ulonglong2*>(&hs[2][rd][16 * qq]);
            uint64_t s0 = 0, s1 = 0, s2 = 0;
#pragma unroll
            for (int i = 0; i < 4; i++) {
                ulonglong2 v0 = q0[i], v1 = q1[i], v2 = q2[i];
                ffma2(s0, v0.x, sU[2 * i]); ffma2(s0, v0.y, sU[2 * i + 1]);
                ffma2(s1, v0.x, sW[2 * i]); ffma2(s1, v0.y, sW[2 * i + 1]);
                ffma2(s1, v1.x, sU[2 * i]); ffma2(s1, v1.y, sU[2 * i + 1]);
                ffma2(s2, v1.x, sW[2 * i]); ffma2(s2, v1.y, sW[2 * i + 1]);
                ffma2(s2, v2.x, sU[2 * i]); ffma2(s2, v2.y, sU[2 * i + 1]);
            }
            float zp0 = hsum2(s0) + xwv64;
            float zp1 = hsum2(s1);
            float zp2 = hsum2(s2);
            if (qq == 3) {                         // row-64 terms
                float h064 = hs[0][rd][64];
                float h164 = hs[1][rd][64];
                float h264 = hs[2][rd][64];
                zp0 = fmaf(u64r, h064, zp0);
                zp1 = fmaf(w64r, h064, fmaf(u64r, h164, zp1));
                zp2 = fmaf(w64r, h164, fmaf(u64r, h264, zp2));
            }
            if (qq == 0) { zp1 += b64; zp2 += b64; }
            zp0 += __shfl_xor_sync(SM, zp0, 1);    // merge quarters
            zp1 += __shfl_xor_sync(SM, zp1, 1);
            zp2 += __shfl_xor_sync(SM, zp2, 1);
            zp0 += __shfl_xor_sync(SM, zp0, 2);
            zp1 += __shfl_xor_sync(SM, zp1, 2);
            zp2 += __shfl_xor_sync(SM, zp2, 2);
            float a640 = act_f(ak64, am64, aa64, zp0);
            float a641 = act_f(ak64, am64, aa64, zp1);
            float a642 = act_f(ak64, am64, aa64, zp2);
            float f640 = __shfl_sync(SM, a640, 4);
            float g640 = __shfl_sync(SM, a640, 8);
            float o640 = __shfl_sync(SM, a640, 12);
            float f641 = __shfl_sync(SM, a641, 4);
            float g641 = __shfl_sync(SM, a641, 8);
            float o641 = __shfl_sync(SM, a641, 12);
            float f642 = __shfl_sync(SM, a642, 4);
            float g642 = __shfl_sync(SM, a642, 8);
            float o642 = __shfl_sync(SM, a642, 12);
            if (tid == 0) {                        // lane 0: g64==0 -> own act = i
                if (w < T_) {
                    c640 = fmaf(f640, c640, a640 * g640);
                    hs[0][wr][64] = o640 * tanh_fast(c640);
                }
                if (w >= 1 && w <= T_) {
                    c641 = fmaf(f641, c641, a641 * g641);
                    hs[1][wr][64] = o641 * tanh_fast(c641);
                }
                if (w >= 2) {
                    c642 = fmaf(f642, c642, a642 * g642);
                    float hn = o642 * tanh_fast(c642);
                    hs[2][wr][64] = hn;
                    hout[(size_t)(w - 2) * D_ + 64] = hn;
                }
            }
        }

        // ---- main cell/hidden updates (writer lanes g==0) ---------------
        if (g == 0) {
            if (w < T_) {
                c0 = fmaf(f0, c0, act0 * g0);
                hs[0][wr][j] = o0 * tanh_fast(c0);
            }
            if (w >= 1 && w <= T_) {
                c1 = fmaf(f1, c1, act1 * g1);
                hs[1][wr][j] = o1 * tanh_fast(c1);
            }
            if (w >= 2) {
                c2 = fmaf(f2, c2, act2 * g2);
                float hn = o2 * tanh_fast(c2);
                hs[2][wr][j] = hn;
                hout[(size_t)(w - 2) * D_ + j] = hn;
            }
        }
        __syncthreads();                           // one barrier per wave
        xwv = xwn;
        xwv64 = xwn64;
    }
}

// ---------------------------------------------------------------------------
// Dense(65): out[r,:] = g_hs[r,:] @ Wd + bd
// ---------------------------------------------------------------------------
__global__ void __launch_bounds__(520, 1) dense_kernel(
    const float* __restrict__ Wd,
    const float* __restrict__ bd,
    float* __restrict__ out)
{
    __shared__ __align__(16) float hrow[DR][68];
    const int tx  = threadIdx.x;
    const int ty  = threadIdx.y;
    const int tid = ty * D_ + tx;

    uint64_t Wc[34];
#pragma unroll
    for (int i = 0; i < 34; i++) {
        int k0 = 2 * i, k1 = 2 * i + 1;
        float w0 = (k0 < D_) ? Wd[(size_t)k0 * D_ + tx] : 0.0f;
        float w1 = (k1 < D_) ? Wd[(size_t)k1 * D_ + tx] : 0.0f;
        Wc[i] = pack2(w0, w1);
    }
    const float bc = bd[tx];
    const size_t row0 = (size_t)blockIdx.x * DR;

    for (int i = tid; i < DR * 68; i += 520) {
        int r = i / 68, cc = i % 68;
        hrow[r][cc] = (cc < D_) ? g_hs[(row0 + r) * D_ + cc] : 0.0f;
    }
    __syncthreads();

    for (int r = ty; r < DR; r += 8)
        out[(row0 + r) * D_ + tx] = bc + dot68(hrow[r], Wc);
}

// ---------------------------------------------------------------------------
extern "C" void kernel_launch(void* const* d_in, const int* in_sizes, int n_in,
                              void* d_out, int out_size)
{
    const float* x  = (const float*)d_in[0];
    const float* W  = (const float*)d_in[1];
    const float* U  = (const float*)d_in[2];
    const float* b  = (const float*)d_in[3];
    const float* Wd = (const float*)d_in[4];
    const float* bd = (const float*)d_in[5];
    float* out = (float*)d_out;

    gemm_xw_kernel<<<BT / GR, G4>>>(x, W, b);
    dummy_kernel<<<1, 32>>>();     // keep ncu capture slot (idx 3) on lstm
    dummy_kernel<<<1, 32>>>();
    lstm_kernel<<<B_, 256>>>(W, U, b);
    dense_kernel<<<BT / DR, dim3(D_, 8)>>>(Wd, bd, out);
}

// round 17
// speedup vs baseline: 1.5782x; 1.0067x over previous
#include <cuda_runtime.h>
#include <cstdint>

#define B_  50
#define T_  2048
#define D_  65
#define G4  260
#define BT  (B_ * T_)
#define KPH 72          // hs row padding: two halves of 36
#define KH  36
#define NL  3
#define NW  (T_ + 2)
#define GR  128
#define DR  64

#if defined(__CUDACC_VER_MAJOR__) && (__CUDACC_VER_MAJOR__ > 12 || (__CUDACC_VER_MAJOR__ == 12 && __CUDACC_VER_MINOR__ >= 4))
#define LSTM_NREG __maxnreg__(248)
#else
#define LSTM_NREG
#endif

__device__ float g_xw[(size_t)BT * G4];   // x@W + b
__device__ float g_hs[(size_t)BT * D_];   // top-layer h

// ---------------------------------------------------------------------------
__device__ __forceinline__ void ffma2(uint64_t& acc, uint64_t a, uint64_t b) {
    asm("fma.rn.f32x2 %0, %1, %2, %0;" : "+l"(acc) : "l"(a), "l"(b));
}
__device__ __forceinline__ uint64_t fadd2(uint64_t a, uint64_t b) {
    uint64_t r;
    asm("add.rn.f32x2 %0, %1, %2;" : "=l"(r) : "l"(a), "l"(b));
    return r;
}
__device__ __forceinline__ float hsum2(uint64_t v) {
    float lo, hi;
    asm("mov.b64 {%0, %1}, %2;" : "=f"(lo), "=f"(hi) : "l"(v));
    return lo + hi;
}
__device__ __forceinline__ uint64_t pack2(float lo, float hi) {
    uint64_t r;
    asm("mov.b64 %0, {%1, %2};" : "=l"(r) : "f"(lo), "f"(hi));
    return r;
}
__device__ __forceinline__ float tanh_fast(float x) {
    float e = __expf(2.0f * x);
    return fmaf(-2.0f, __fdividef(1.0f, 1.0f + e), 1.0f);
}
__device__ __forceinline__ float act_f(float k, float m, float a, float z) {
    return fmaf(m, __fdividef(1.0f, 1.0f + __expf(k * z)), a);
}
__device__ __forceinline__ float sigm_f(float z) {
    return __fdividef(1.0f, 1.0f + __expf(-z));
}

__device__ __forceinline__ void load_col(uint64_t* Wc,
                                         const float* __restrict__ M, int col) {
#pragma unroll
    for (int i = 0; i < 34; i++) {
        int k0 = 2 * i, k1 = 2 * i + 1;
        float w0 = (k0 < D_) ? M[(size_t)k0 * G4 + col] : 0.0f;
        float w1 = (k1 < D_) ? M[(size_t)k1 * G4 + col] : 0.0f;
        Wc[i] = pack2(w0, w1);
    }
}
__device__ __forceinline__ void load_half_col(uint64_t* Wc,
                                              const float* __restrict__ M,
                                              int col, int half) {
    const int rb = KH * half;
#pragma unroll
    for (int i = 0; i < 18; i++) {
        int k0 = rb + 2 * i, k1 = k0 + 1;
        float w0 = (k0 < D_) ? M[(size_t)k0 * G4 + col] : 0.0f;
        float w1 = (k1 < D_) ? M[(size_t)k1 * G4 + col] : 0.0f;
        Wc[i] = pack2(w0, w1);
    }
}

__device__ __forceinline__ float dot68(const float* __restrict__ src,
                                       const uint64_t* __restrict__ Wc) {
    uint64_t a0 = 0, a1 = 0;
    const ulonglong2* s2 = reinterpret_cast<const ulonglong2*>(src);
#pragma unroll
    for (int i = 0; i < 17; i++) {
        ulonglong2 v = s2[i];
        ffma2(a0, v.x, Wc[2 * i]);
        ffma2(a1, v.y, Wc[2 * i + 1]);
    }
    return hsum2(fadd2(a0, a1));
}

// ---------------------------------------------------------------------------
__global__ void dummy_kernel() {}

// ---------------------------------------------------------------------------
// GEMM: g_xw[r, c] = x[r,:] @ W[:,c] + b[c]
// ---------------------------------------------------------------------------
__global__ void __launch_bounds__(G4, 2) gemm_xw_kernel(
    const float* __restrict__ x, const float* __restrict__ W,
    const float* __restrict__ b)
{
    __shared__ __align__(16) float xs[2][32][68];
    const int c = threadIdx.x;
    uint64_t Wc[34];
    load_col(Wc, W, c);
    const float bc = b[c];
    const size_t row0 = (size_t)blockIdx.x * GR;

    for (int i = c; i < 32 * 68; i += G4) {
        int r = i / 68, cc = i % 68;
        xs[0][r][cc] = (cc < D_) ? x[(row0 + r) * D_ + cc] : 0.0f;
    }
    __syncthreads();

    for (int ch = 0; ch < GR / 32; ch++) {
        int buf = ch & 1;
        if (ch + 1 < GR / 32) {
            for (int i = c; i < 32 * 68; i += G4) {
                int r = i / 68, cc = i % 68;
                xs[buf ^ 1][r][cc] =
                    (cc < D_) ? x[(row0 + (ch + 1) * 32 + r) * D_ + cc] : 0.0f;
            }
        }
        for (int r = 0; r < 32; r++)
            g_xw[(row0 + ch * 32 + r) * G4 + c] = bc + dot68(xs[buf][r], Wc);
        __syncthreads();
    }
}

// ---------------------------------------------------------------------------
// LSTM wavefront, 256 threads, C=2 cols x half-K per thread.
// tid = 4*unit + 2*gatepair + khalf; units 0..63 main, unit 64 sidecar
// (warp 0 lanes 0..15, as in R16). Per-thread LDS.128: 27 (vs 51).
// ---------------------------------------------------------------------------
__global__ void LSTM_NREG lstm_kernel(
    const float* __restrict__ W,
    const float* __restrict__ U,
    const float* __restrict__ b)
{
    __shared__ __align__(16) float hs[NL][2][KPH];

    const int tid  = threadIdx.x;        // 0..255
    const int bb   = blockIdx.x;
    const int j    = tid >> 2;           // unit 0..63
    const int s    = (tid >> 1) & 1;     // gate pair: 0 -> (i,f), 1 -> (g,o)
    const int h    = tid & 1;            // K-half
    const unsigned FULL = 0xFFFFFFFFu;
    const int colA = (2 * s)     * D_ + j;
    const int colB = (2 * s + 1) * D_ + j;
    const int hb   = KH * h;

    uint64_t WcA[18], WcB[18], UcA[18], UcB[18];
    load_half_col(WcA, W, colA, h);
    load_half_col(WcB, W, colB, h);
    load_half_col(UcA, U, colA, h);
    load_half_col(UcB, U, colB, h);
    const float bA = (h == 0) ? b[colA] : 0.0f;
    const float bB = (h == 0) ? b[colB] : 0.0f;
    // col A activation: s=0 -> i (sigmoid), s=1 -> g (tanh). col B: sigmoid.
    const float akA = s ?  2.0f : -1.0f;
    const float amA = s ? -2.0f :  1.0f;
    const float aaA = s ?  1.0f :  0.0f;

    // ---- sidecar setup (unit 64): warp 0 lanes 0..15, K-quarters ---------
    const bool side = (tid < 16);
    const int g64 = (tid >> 2) & 3;
    const int qq  = tid & 3;
    const int col64 = g64 * D_ + 64;
    uint64_t sW[8], sU[8];
#pragma unroll
    for (int i = 0; i < 8; i++) {
        int k0 = qq * 16 + 2 * i, k1 = k0 + 1;
        sW[i] = side ? pack2(W[(size_t)k0 * G4 + col64],
                             W[(size_t)k1 * G4 + col64]) : 0;
        sU[i] = side ? pack2(U[(size_t)k0 * G4 + col64],
                             U[(size_t)k1 * G4 + col64]) : 0;
    }
    float w64r = 0.f, u64r = 0.f;
    if (side && qq == 3) {
        w64r = W[(size_t)64 * G4 + col64];
        u64r = U[(size_t)64 * G4 + col64];
    }
    const float b64  = b[col64];
    const float ak64 = (g64 == 2) ?  2.0f : -1.0f;
    const float am64 = (g64 == 2) ? -2.0f :  1.0f;
    const float aa64 = (g64 == 2) ?  1.0f :  0.0f;

    for (int i = tid; i < NL * 2 * KPH; i += 256) ((float*)hs)[i] = 0.0f;
    float c0 = 0.f, c1 = 0.f, c2 = 0.f;          // writer lanes (tid&3)==0
    float c640 = 0.f, c641 = 0.f, c642 = 0.f;    // tid==0

    const float* xwpA  = g_xw + (size_t)bb * T_ * G4 + colA;
    const float* xwpB  = g_xw + (size_t)bb * T_ * G4 + colB;
    const float* xwp64 = g_xw + (size_t)bb * T_ * G4 + col64;
    float*       hout  = g_hs + (size_t)bb * T_ * D_;
    float xwvA = (h == 0) ? xwpA[0] : 0.0f;
    float xwvB = (h == 0) ? xwpB[0] : 0.0f;
    float xwv64 = (side && qq == 0) ? xwp64[0] : 0.0f;
    __syncthreads();

    for (int w = 0; w < NW; w++) {
        const int rd = (w & 1) ^ 1;
        const int wr = w & 1;
        const int tpf = (w + 1 < T_) ? (w + 1) : (T_ - 1);
        float xwnA = (h == 0) ? xwpA[(size_t)tpf * G4] : 0.0f;
        float xwnB = (h == 0) ? xwpB[(size_t)tpf * G4] : 0.0f;
        float xwn64 = (side && qq == 0) ? xwp64[(size_t)tpf * G4] : 0.0f;

        // ---- 10 half-dot chains over 3 shared vectors --------------------
        uint64_t Aa = 0, Ba = 0, Ea = 0, Da = 0, Fa = 0;  // col A
        uint64_t Ab = 0, Bb = 0, Eb = 0, Db = 0, Fb = 0;  // col B
        {
            const ulonglong2* p0 =
                reinterpret_cast<const ulonglong2*>(&hs[0][rd][hb]);
            const ulonglong2* p1 =
                reinterpret_cast<const ulonglong2*>(&hs[1][rd][hb]);
            const ulonglong2* p2 =
                reinterpret_cast<const ulonglong2*>(&hs[2][rd][hb]);
#pragma unroll
            for (int i = 0; i < 9; i++) {
                ulonglong2 v0 = p0[i], v1 = p1[i], v2 = p2[i];
                uint64_t ua0 = UcA[2 * i], ua1 = UcA[2 * i + 1];
                uint64_t wa0 = WcA[2 * i], wa1 = WcA[2 * i + 1];
                uint64_t ub0 = UcB[2 * i], ub1 = UcB[2 * i + 1];
                uint64_t wb0 = WcB[2 * i], wb1 = WcB[2 * i + 1];
                ffma2(Aa, v0.x, ua0); ffma2(Aa, v0.y, ua1);   // l0: U.h0
                ffma2(Ba, v0.x, wa0); ffma2(Ba, v0.y, wa1);   // l1: W.h0
                ffma2(Ea, v1.x, ua0); ffma2(Ea, v1.y, ua1);   // l1: U.h1
                ffma2(Da, v1.x, wa0); ffma2(Da, v1.y, wa1);   // l2: W.h1
                ffma2(Fa, v2.x, ua0); ffma2(Fa, v2.y, ua1);   // l2: U.h2
                ffma2(Ab, v0.x, ub0); ffma2(Ab, v0.y, ub1);
                ffma2(Bb, v0.x, wb0); ffma2(Bb, v0.y, wb1);
                ffma2(Eb, v1.x, ub0); ffma2(Eb, v1.y, ub1);
                ffma2(Db, v1.x, wb0); ffma2(Db, v1.y, wb1);
                ffma2(Fb, v2.x, ub0); ffma2(Fb, v2.y, ub1);
            }
        }
        float zA0 = xwvA + hsum2(Aa);
        float zA1 = bA + hsum2(Ba) + hsum2(Ea);
        float zA2 = bA + hsum2(Da) + hsum2(Fa);
        float zB0 = xwvB + hsum2(Ab);
        float zB1 = bB + hsum2(Bb) + hsum2(Eb);
        float zB2 = bB + hsum2(Db) + hsum2(Fb);
        // merge K-halves
        zA0 += __shfl_xor_sync(FULL, zA0, 1);
        zA1 += __shfl_xor_sync(FULL, zA1, 1);
        zA2 += __shfl_xor_sync(FULL, zA2, 1);
        zB0 += __shfl_xor_sync(FULL, zB0, 1);
        zB1 += __shfl_xor_sync(FULL, zB1, 1);
        zB2 += __shfl_xor_sync(FULL, zB2, 1);

        // activations: A = gate 2s, B = gate 2s+1 (sigmoid)
        float aA0 = act_f(akA, amA, aaA, zA0);
        float aA1 = act_f(akA, amA, aaA, zA1);
        float aA2 = act_f(akA, amA, aaA, zA2);
        float aB0 = sigm_f(zB0);
        float aB1 = sigm_f(zB1);
        float aB2 = sigm_f(zB2);

        // pair exchange across s (xor 2): s=0 gets (g,o), s=1 gets (i,f)
        float pA0 = __shfl_xor_sync(FULL, aA0, 2);
        float pB0 = __shfl_xor_sync(FULL, aB0, 2);
        float pA1 = __shfl_xor_sync(FULL, aA1, 2);
        float pB1 = __shfl_xor_sync(FULL, aB1, 2);
        float pA2 = __shfl_xor_sync(FULL, aA2, 2);
        float pB2 = __shfl_xor_sync(FULL, aB2, 2);

        // ---- sidecar: unit 64 (same as R16) ------------------------------
        if (side) {
            const unsigned SM = 0xFFFFu;
            const ulonglong2* q0 =
                reinterpret_cast<const ulonglong2*>(&hs[0][rd][16 * qq]);
            const ulonglong2* q1 =
                reinterpret_cast<const ulonglong2*>(&hs[1][rd][16 * qq]);
            const ulonglong2* q2 =
                reinterpret_cast<const ulonglong2*>(&hs[2][rd][16 * qq]);
            uint64_t s0 = 0, s1 = 0, s2 = 0;
#pragma unroll
            for (int i = 0; i < 4; i++) {
                ulonglong2 v0 = q0[i], v1 = q1[i], v2 = q2[i];
                ffma2(s0, v0.x, sU[2 * i]); ffma2(s0, v0.y, sU[2 * i + 1]);
                ffma2(s1, v0.x, sW[2 * i]); ffma2(s1, v0.y, sW[2 * i + 1]);
                ffma2(s1, v1.x, sU[2 * i]); ffma2(s1, v1.y, sU[2 * i + 1]);
                ffma2(s2, v1.x, sW[2 * i]); ffma2(s2, v1.y, sW[2 * i + 1]);
                ffma2(s2, v2.x, sU[2 * i]); ffma2(s2, v2.y, sU[2 * i + 1]);
            }
            float zp0 = hsum2(s0) + xwv64;
            float zp1 = hsum2(s1);
            float zp2 = hsum2(s2);
            if (qq == 3) {
                float h064 = hs[0][rd][64];
                float h164 = hs[1][rd][64];
                float h264 = hs[2][rd][64];
                zp0 = fmaf(u64r, h064, zp0);
                zp1 = fmaf(w64r, h064, fmaf(u64r, h164, zp1));
                zp2 = fmaf(w64r, h164, fmaf(u64r, h264, zp2));
            }
            if (qq == 0) { zp1 += b64; zp2 += b64; }
            zp0 += __shfl_xor_sync(SM, zp0, 1);
            zp1 += __shfl_xor_sync(SM, zp1, 1);
            zp2 += __shfl_xor_sync(SM, zp2, 1);
            zp0 += __shfl_xor_sync(SM, zp0, 2);
            zp1 += __shfl_xor_sync(SM, zp1, 2);
            zp2 += __shfl_xor_sync(SM, zp2, 2);
            float a640 = act_f(ak64, am64, aa64, zp0);
            float a641 = act_f(ak64, am64, aa64, zp1);
            float a642 = act_f(ak64, am64, aa64, zp2);
            float f640 = __shfl_sync(SM, a640, 4);
            float g640 = __shfl_sync(SM, a640, 8);
            float o640 = __shfl_sync(SM, a640, 12);
            float f641 = __shfl_sync(SM, a641, 4);
            float g641 = __shfl_sync(SM, a641, 8);
            float o641 = __shfl_sync(SM, a641, 12);
            float f642 = __shfl_sync(SM, a642, 4);
            float g642 = __shfl_sync(SM, a642, 8);
            float o642 = __shfl_sync(SM, a642, 12);
            if (tid == 0) {
                if (w < T_) {
                    c640 = fmaf(f640, c640, a640 * g640);
                    hs[0][wr][64] = o640 * tanh_fast(c640);
                }
                if (w >= 1 && w <= T_) {
                    c641 = fmaf(f641, c641, a641 * g641);
                    hs[1][wr][64] = o641 * tanh_fast(c641);
                }
                if (w >= 2) {
                    c642 = fmaf(f642, c642, a642 * g642);
                    float hn = o642 * tanh_fast(c642);
                    hs[2][wr][64] = hn;
                    hout[(size_t)(w - 2) * D_ + 64] = hn;
                }
            }
        }

        // ---- main updates: writer = s=0, h=0 lane; i=aA*, f=aB*, g=pA*, o=pB*
        if ((tid & 3) == 0) {
            if (w < T_) {
                c0 = fmaf(aB0, c0, aA0 * pA0);
                hs[0][wr][j] = pB0 * tanh_fast(c0);
            }
            if (w >= 1 && w <= T_) {
                c1 = fmaf(aB1, c1, aA1 * pA1);
                hs[1][wr][j] = pB1 * tanh_fast(c1);
            }
            if (w >= 2) {
                c2 = fmaf(aB2, c2, aA2 * pA2);
                float hn = pB2 * tanh_fast(c2);
                hs[2][wr][j] = hn;
                hout[(size_t)(w - 2) * D_ + j] = hn;
            }
        }
        __syncthreads();
        xwvA = xwnA; xwvB = xwnB; xwv64 = xwn64;
    }
}

// ---------------------------------------------------------------------------
// Dense(65): out[r,:] = g_hs[r,:] @ Wd + bd
// ---------------------------------------------------------------------------
__global__ void __launch_bounds__(520, 1) dense_kernel(
    const float* __restrict__ Wd,
    const float* __restrict__ bd,
    float* __restrict__ out)
{
    __shared__ __align__(16) float hrow[DR][68];
    const int tx  = threadIdx.x;
    const int ty  = threadIdx.y;
    const int tid = ty * D_ + tx;

    uint64_t Wc[34];
#pragma unroll
    for (int i = 0; i < 34; i++) {
        int k0 = 2 * i, k1 = 2 * i + 1;
        float w0 = (k0 < D_) ? Wd[(size_t)k0 * D_ + tx] : 0.0f;
        float w1 = (k1 < D_) ? Wd[(size_t)k1 * D_ + tx] : 0.0f;
        Wc[i] = pack2(w0, w1);
    }
    const float bc = bd[tx];
    const size_t row0 = (size_t)blockIdx.x * DR;

    for (int i = tid; i < DR * 68; i += 520) {
        int r = i / 68, cc = i % 68;
        hrow[r][cc] = (cc < D_) ? g_hs[(row0 + r) * D_ + cc] : 0.0f;
    }
    __syncthreads();

    for (int r = ty; r < DR; r += 8)
        out[(row0 + r) * D_ + tx] = bc + dot68(hrow[r], Wc);
}

// ---------------------------------------------------------------------------
extern "C" void kernel_launch(void* const* d_in, const int* in_sizes, int n_in,
                              void* d_out, int out_size)
{
    const float* x  = (const float*)d_in[0];
    const float* W  = (const float*)d_in[1];
    const float* U  = (const float*)d_in[2];
    const float* b  = (const float*)d_in[3];
    const float* Wd = (const float*)d_in[4];
    const float* bd = (const float*)d_in[5];
    float* out = (float*)d_out;

    gemm_xw_kernel<<<BT / GR, G4>>>(x, W, b);
    dummy_kernel<<<1, 32>>>();     // keep ncu capture slot (idx 3) on lstm
    dummy_kernel<<<1, 32>>>();
    lstm_kernel<<<B_, 256>>>(W, U, b);
    dense_kernel<<<BT / DR, dim3(D_, 8)>>>(Wd, bd, out);
}